// round 17
// baseline (speedup 1.0000x reference)
#include <cuda_runtime.h>

// ---------------------------------------------------------------------------
// MyRNN: 2-layer tanh RNN, B=4096, T=512, H=32, input dim 1, + Linear(32->1).
//
// Round-16: latency attack on the R15 tensor-core kernel.
//   - 4 batches per warp -> 1024 independent single-warp CTAs (6.9/SM,
//     single wave, 1.73 warps/SMSP) -- doubles latency hiding. n=8 MMA keeps
//     4 padded columns (zero-init, clamped x pointers; tanh keeps finite).
//   - layer1 accumulator split (d1a: Wih1*h0, d1b: Whh1*h1) -> longest
//     dependent HMMA chain 12 -> 6; six independent 6-deep chains per warp.
//   - split-precision bf16 mma (W*h ~= Whi*hhi + Whi*hlo + Wlo*hhi), fp32 acc.
//   - layer1 skewed one step behind layer0; ONE __syncwarp per step.
// ---------------------------------------------------------------------------

typedef unsigned int u32;

#define B_TOT 4096
#define T_TOT 512
#define H     32
#define NBW   4                  // real batches per warp
#define NCTAS (B_TOT / NBW)      // 1024
#define SROW  36                 // padded row stride (floats) for h smem [b][k]

// pack two f32 -> bf16x2 ; first arg -> LOW half, second -> HIGH half
__device__ __forceinline__ u32 bf16pair(float flo, float fhi) {
    u32 d;
    asm("cvt.rn.bf16x2.f32 %0, %1, %2;" : "=r"(d) : "f"(fhi), "f"(flo));
    return d;
}
__device__ __forceinline__ float lo_f32(u32 p) { return __uint_as_float(p << 16); }
__device__ __forceinline__ float hi_f32(u32 p) { return __uint_as_float(p & 0xffff0000u); }

struct Frag { u32 h[4]; u32 l[4]; };   // A-fragment (16x16 bf16), hi + lo parts

__device__ __forceinline__ void mma_bf16(float* d, const u32* a, const u32* b) {
    asm("mma.sync.aligned.m16n8k16.row.col.f32.bf16.bf16.f32 "
        "{%0,%1,%2,%3}, {%4,%5,%6,%7}, {%8,%9}, {%0,%1,%2,%3};"
        : "+f"(d[0]), "+f"(d[1]), "+f"(d[2]), "+f"(d[3])
        : "r"(a[0]), "r"(a[1]), "r"(a[2]), "r"(a[3]), "r"(b[0]), "r"(b[1]));
}

__device__ __forceinline__ float tanh_fast(float x) {
    float e = __expf(2.0f * x);
    return __fdividef(e - 1.0f, e + 1.0f);
}

// Load A-fragment (hi/lo) of 32x32 row-major W, tile (mt, kt).
__device__ __forceinline__ Frag load_frag(const float* __restrict__ W,
                                          int mt, int kt, int g, int tu) {
    Frag f;
    const int r0 = 16 * mt + g, r1 = r0 + 8, c = 16 * kt + 2 * tu;
    float v[8];
    v[0] = W[r0 * H + c];     v[1] = W[r0 * H + c + 1];
    v[2] = W[r1 * H + c];     v[3] = W[r1 * H + c + 1];
    v[4] = W[r0 * H + c + 8]; v[5] = W[r0 * H + c + 9];
    v[6] = W[r1 * H + c + 8]; v[7] = W[r1 * H + c + 9];
#pragma unroll
    for (int q = 0; q < 4; q++) {
        f.h[q] = bf16pair(v[2 * q], v[2 * q + 1]);
        f.l[q] = bf16pair(v[2 * q] - lo_f32(f.h[q]), v[2 * q + 1] - hi_f32(f.h[q]));
    }
    return f;
}

// Build B-fragments (hi/lo) for h (32 k x 8 n) from smem [n][k] (stride SROW).
__device__ __forceinline__ void build_b(u32 bh[2][2], u32 bl[2][2],
                                        const float* __restrict__ hsm, int g, int tu) {
#pragma unroll
    for (int kt = 0; kt < 2; kt++) {
        float f0 = hsm[g * SROW + 16 * kt + 2 * tu];
        float f1 = hsm[g * SROW + 16 * kt + 2 * tu + 1];
        float f2 = hsm[g * SROW + 16 * kt + 2 * tu + 8];
        float f3 = hsm[g * SROW + 16 * kt + 2 * tu + 9];
        bh[kt][0] = bf16pair(f0, f1);
        bh[kt][1] = bf16pair(f2, f3);
        bl[kt][0] = bf16pair(f0 - lo_f32(bh[kt][0]), f1 - hi_f32(bh[kt][0]));
        bl[kt][1] = bf16pair(f2 - lo_f32(bh[kt][1]), f3 - hi_f32(bh[kt][1]));
    }
}

// One split matvec: d += W * h  (3 mma terms per (mt, kt))
__device__ __forceinline__ void mv(float d[2][4], const Frag W[2][2],
                                   const u32 bh[2][2], const u32 bl[2][2]) {
#pragma unroll
    for (int mt = 0; mt < 2; mt++)
#pragma unroll
        for (int kt = 0; kt < 2; kt++) {
            mma_bf16(d[mt], W[mt][kt].h, bh[kt]);
            mma_bf16(d[mt], W[mt][kt].h, bl[kt]);
            mma_bf16(d[mt], W[mt][kt].l, bh[kt]);
        }
}

// Store tanh'd D values (2 tiles x 4 regs) to smem [n][k].
__device__ __forceinline__ void store_h(float* __restrict__ hsm, int g, int tu,
                                        const float v[2][4]) {
#pragma unroll
    for (int mt = 0; mt < 2; mt++) {
        hsm[(2 * tu + 0) * SROW + g + 16 * mt]     = v[mt][0];
        hsm[(2 * tu + 1) * SROW + g + 16 * mt]     = v[mt][1];
        hsm[(2 * tu + 0) * SROW + g + 8 + 16 * mt] = v[mt][2];
        hsm[(2 * tu + 1) * SROW + g + 8 + 16 * mt] = v[mt][3];
    }
}

__global__ void __launch_bounds__(32, 7)
rnn_kernel(const float* __restrict__ x,
           const float* __restrict__ hstate,
           const float* __restrict__ Wih0, const float* __restrict__ Whh0,
           const float* __restrict__ bih0, const float* __restrict__ bhh0,
           const float* __restrict__ Wih1, const float* __restrict__ Whh1,
           const float* __restrict__ bih1, const float* __restrict__ bhh1,
           const float* __restrict__ Wfc,  const float* __restrict__ bfc,
           float* __restrict__ out)
{
    // [buffer][layer][8 n-columns x SROW]  (n-cols 4..7 are padding)
    __shared__ float HSm[2][2][8 * SROW];

    const int lane = threadIdx.x;
    const int g    = lane >> 2;     // 0..7  (n column / m row group)
    const int tu   = lane & 3;      // 0..3
    const int b0   = blockIdx.x * NBW;

    // ---- persistent weight fragments (hi+lo): 96 regs ----
    Frag w0[2][2], wa[2][2], wb[2][2];
#pragma unroll
    for (int mt = 0; mt < 2; mt++)
#pragma unroll
        for (int kt = 0; kt < 2; kt++) {
            w0[mt][kt] = load_frag(Whh0, mt, kt, g, tu);
            wa[mt][kt] = load_frag(Wih1, mt, kt, g, tu);
            wb[mt][kt] = load_frag(Whh1, mt, kt, g, tu);
        }

    // per-thread biases / input weights at rows r0 = g+16mt, r1 = r0+8
    float bia0[2][2], bia1[2][2], wx[2][2];
#pragma unroll
    for (int mt = 0; mt < 2; mt++) {
        int r0 = g + 16 * mt, r1 = r0 + 8;
        bia0[mt][0] = bih0[r0] + bhh0[r0];
        bia0[mt][1] = bih0[r1] + bhh0[r1];
        bia1[mt][0] = bih1[r0] + bhh1[r0];
        bia1[mt][1] = bih1[r1] + bhh1[r1];
        wx[mt][0] = Wih0[r0];
        wx[mt][1] = Wih0[r1];
    }

    // x pointers: columns 2tu, 2tu+1 folded into the 4 real batches
    const float* px0 = x + (size_t)(b0 + ((2 * tu) & 3)) * T_TOT;
    const float* px1 = x + (size_t)(b0 + ((2 * tu + 1) & 3)) * T_TOT;

    // ---- initial state: h0init -> buf1/layer0, h1init -> buf0/layer1 ----
    // lane covers n = g, k = 8*tu..8*tu+7 ; padded columns (g>=4) -> 0
#pragma unroll
    for (int kk = 0; kk < 8; kk++) {
        int k = 8 * tu + kk;
        float v0 = (g < NBW) ? hstate[(b0 + g) * H + k] : 0.0f;
        float v1 = (g < NBW) ? hstate[B_TOT * H + (b0 + g) * H + k] : 0.0f;
        HSm[1][0][g * SROW + k] = v0;
        HSm[0][1][g * SROW + k] = v1;
    }
    __syncwarp();

    float h0v[2][4], h1v[2][4];

    // =================== i = 0 : layer0 only ===================
    {
        float xa = __ldg(px0 + 0), xb = __ldg(px1 + 0);
        u32 b0h[2][2], b0l[2][2];
        build_b(b0h, b0l, &HSm[1][0][0], g, tu);
        float d0[2][4];
#pragma unroll
        for (int mt = 0; mt < 2; mt++) {
            d0[mt][0] = fmaf(wx[mt][0], xa, bia0[mt][0]);
            d0[mt][1] = fmaf(wx[mt][0], xb, bia0[mt][0]);
            d0[mt][2] = fmaf(wx[mt][1], xa, bia0[mt][1]);
            d0[mt][3] = fmaf(wx[mt][1], xb, bia0[mt][1]);
        }
        mv(d0, w0, b0h, b0l);
#pragma unroll
        for (int mt = 0; mt < 2; mt++)
#pragma unroll
            for (int q = 0; q < 4; q++) h0v[mt][q] = tanh_fast(d0[mt][q]);
        store_h(&HSm[0][0][0], g, tu, h0v);
        __syncwarp();
    }

    // =================== main loop i = 1 .. T-1 ===================
    // read buf (i-1)&1 : { h0(i-1), h1(i-2) } ; write buf i&1 : { h0(i), h1(i-1) }
#pragma unroll 1
    for (int i = 1; i < T_TOT; i++) {
        const int rp = (i - 1) & 1, wp = i & 1;
        float xa = __ldg(px0 + i), xb = __ldg(px1 + i);

        u32 b0h[2][2], b0l[2][2], b1h[2][2], b1l[2][2];
        build_b(b0h, b0l, &HSm[rp][0][0], g, tu);
        build_b(b1h, b1l, &HSm[rp][1][0], g, tu);

        float d0[2][4], d1a[2][4], d1b[2][4];
#pragma unroll
        for (int mt = 0; mt < 2; mt++) {
            d0[mt][0] = fmaf(wx[mt][0], xa, bia0[mt][0]);
            d0[mt][1] = fmaf(wx[mt][0], xb, bia0[mt][0]);
            d0[mt][2] = fmaf(wx[mt][1], xa, bia0[mt][1]);
            d0[mt][3] = fmaf(wx[mt][1], xb, bia0[mt][1]);
            d1a[mt][0] = bia1[mt][0];
            d1a[mt][1] = bia1[mt][0];
            d1a[mt][2] = bia1[mt][1];
            d1a[mt][3] = bia1[mt][1];
            d1b[mt][0] = 0.0f; d1b[mt][1] = 0.0f;
            d1b[mt][2] = 0.0f; d1b[mt][3] = 0.0f;
        }

        mv(d0,  w0, b0h, b0l);   // layer0: Whh0 * h0(i-1)   (6-deep chains)
        mv(d1a, wa, b0h, b0l);   // layer1: Wih1 * h0(i-1)   (6-deep chains)
        mv(d1b, wb, b1h, b1l);   // layer1: Whh1 * h1(i-2)   (6-deep chains)

#pragma unroll
        for (int mt = 0; mt < 2; mt++)
#pragma unroll
            for (int q = 0; q < 4; q++) {
                h0v[mt][q] = tanh_fast(d0[mt][q]);
                h1v[mt][q] = tanh_fast(d1a[mt][q] + d1b[mt][q]);
            }
        store_h(&HSm[wp][0][0], g, tu, h0v);
        store_h(&HSm[wp][1][0], g, tu, h1v);
        __syncwarp();
    }

    // =================== final : layer1 for step T-1 ===================
    // buf 1 holds { h0(T-1), h1(T-2) }   (last wp = 511&1 = 1)
    {
        u32 b0h[2][2], b0l[2][2], b1h[2][2], b1l[2][2];
        build_b(b0h, b0l, &HSm[1][0][0], g, tu);
        build_b(b1h, b1l, &HSm[1][1][0], g, tu);
        float d1a[2][4], d1b[2][4];
#pragma unroll
        for (int mt = 0; mt < 2; mt++) {
            d1a[mt][0] = bia1[mt][0];
            d1a[mt][1] = bia1[mt][0];
            d1a[mt][2] = bia1[mt][1];
            d1a[mt][3] = bia1[mt][1];
            d1b[mt][0] = 0.0f; d1b[mt][1] = 0.0f;
            d1b[mt][2] = 0.0f; d1b[mt][3] = 0.0f;
        }
        mv(d1a, wa, b0h, b0l);
        mv(d1b, wb, b1h, b1l);
#pragma unroll
        for (int mt = 0; mt < 2; mt++)
#pragma unroll
            for (int q = 0; q < 4; q++)
                h1v[mt][q] = tanh_fast(d1a[mt][q] + d1b[mt][q]);
    }

    // =================== outputs (only real columns tu<2) ===================
    float* h0out = out + B_TOT;
    float* h1out = out + B_TOT + B_TOT * H;
    if (tu < 2) {
        const int c0 = b0 + 2 * tu, c1 = c0 + 1;
#pragma unroll
        for (int mt = 0; mt < 2; mt++) {
            int r0 = g + 16 * mt, r1 = r0 + 8;
            h0out[c0 * H + r0] = h0v[mt][0];
            h0out[c1 * H + r0] = h0v[mt][1];
            h0out[c0 * H + r1] = h0v[mt][2];
            h0out[c1 * H + r1] = h0v[mt][3];
            h1out[c0 * H + r0] = h1v[mt][0];
            h1out[c1 * H + r0] = h1v[mt][1];
            h1out[c0 * H + r1] = h1v[mt][2];
            h1out[c1 * H + r1] = h1v[mt][3];
        }
    }

    // pred[b] = sum_j Wfc[j] * h1[j, b] + bfc
    float pa = 0.0f, pb = 0.0f;
#pragma unroll
    for (int mt = 0; mt < 2; mt++) {
        float wf0 = Wfc[g + 16 * mt], wf1 = Wfc[g + 8 + 16 * mt];
        pa = fmaf(wf0, h1v[mt][0], fmaf(wf1, h1v[mt][2], pa));
        pb = fmaf(wf0, h1v[mt][1], fmaf(wf1, h1v[mt][3], pb));
    }
#pragma unroll
    for (int m = 4; m <= 16; m <<= 1) {
        pa += __shfl_xor_sync(0xffffffffu, pa, m);
        pb += __shfl_xor_sync(0xffffffffu, pb, m);
    }
    if (lane < 2) {                       // lanes 0,1 -> tu 0,1 (g = 0)
        float bf = bfc[0];
        out[b0 + 2 * lane]     = pa + bf;
        out[b0 + 2 * lane + 1] = pb + bf;
    }
}

// ---------------------------------------------------------------------------
extern "C" void kernel_launch(void* const* d_in, const int* in_sizes, int n_in,
                              void* d_out, int out_size)
{
    const float* x      = (const float*)d_in[0];
    const float* hstate = (const float*)d_in[1];
    const float* Wih0   = (const float*)d_in[2];
    const float* Whh0   = (const float*)d_in[3];
    const float* bih0   = (const float*)d_in[4];
    const float* bhh0   = (const float*)d_in[5];
    const float* Wih1   = (const float*)d_in[6];
    const float* Whh1   = (const float*)d_in[7];
    const float* bih1   = (const float*)d_in[8];
    const float* bhh1   = (const float*)d_in[9];
    const float* Wfc    = (const float*)d_in[10];
    const float* bfc    = (const float*)d_in[11];
    float* out          = (float*)d_out;

    rnn_kernel<<<NCTAS, 32>>>(x, hstate, Wih0, Whh0, bih0, bhh0,
                              Wih1, Whh1, bih1, bhh1, Wfc, bfc, out);
}